// round 17
// baseline (speedup 1.0000x reference)
#include <cuda_runtime.h>

#define LOG2PI_F 1.8378770664093454f   // log(2*pi)
#define LOG2E_F  1.4426950408889634f   // log2(e)
#define LN2_F    0.6931471805599453f   // ln(2)

typedef unsigned long long u64;

__device__ __forceinline__ float ex2_fast(float x) {
    float r;
    asm("ex2.approx.ftz.f32 %0, %1;" : "=f"(r) : "f"(x));
    return r;
}
__device__ __forceinline__ u64 pack2(float lo, float hi) {
    u64 r; asm("mov.b64 %0, {%1, %2};" : "=l"(r) : "f"(lo), "f"(hi)); return r;
}
__device__ __forceinline__ void unpack2(u64 v, float& lo, float& hi) {
    asm("mov.b64 {%0, %1}, %2;" : "=f"(lo), "=f"(hi) : "l"(v));
}
__device__ __forceinline__ u64 add2(u64 a, u64 b) {
    u64 r; asm("add.rn.f32x2 %0, %1, %2;" : "=l"(r) : "l"(a), "l"(b)); return r;
}
__device__ __forceinline__ u64 fma2(u64 a, u64 b, u64 c) {
    u64 r; asm("fma.rn.f32x2 %0, %1, %2, %3;" : "=l"(r) : "l"(a), "l"(b), "l"(c)); return r;
}

// Quadratic-form GMM: arg_c(z) = A z0^2 + B z0 z1 + C z1^2 + D z0 + E z1 + F
// (base-2 exponent).  pdf = sum_c 2^{arg_c}.
// grad0 = ln2 * (2 z0 * SeA + z1 * SeB + SeD); grad1 = ln2 * (z0 * SeB + 2 z1 * SeC + SeE)
// Each thread: TWO batch points (b, b+B/2), packed lane-wise into f32x2 ops.
// Params splatted in smem so LDS.128 yields ready (p,p) pairs.
__global__ __launch_bounds__(64)
void recovery_policy_kernel(
    const float* __restrict__ z,      // [B,K,2]
    const float* __restrict__ w,      // [K,C]
    const float* __restrict__ mu,     // [K,C,2]
    const float* __restrict__ cov,    // [K,C,2,2]
    const float* __restrict__ scale,  // [K,2]
    float* __restrict__ out,
    int B, int K, int C, int gradOff)
{
    const int k   = blockIdx.y;
    const int tid = threadIdx.x;

    // splatted packed coeffs: s1 = {(A,A),(B,B)}, s2 = {(C,C),(D,D)}, s3 = {(E,E),(F,F)}
    __shared__ ulonglong2 s1[64];
    __shared__ ulonglong2 s2[64];
    __shared__ ulonglong2 s3[64];
    __shared__ float2 s_scale;

    if (tid < C) {
        const int idx = k * C + tid;
        const float4 cv = ((const float4*)cov)[idx];      // a b c d (2x2 row-major)
        const float det  = cv.x * cv.w - cv.y * cv.z;
        const float rdet = 1.0f / det;
        const float i00 =  cv.w * rdet;
        const float i01 = -cv.y * rdet;
        const float i11 =  cv.x * rdet;
        const float2 m  = ((const float2*)mu)[idx];
        const float c2  = (logf(w[idx]) - 0.5f * logf(det) - LOG2PI_F) * LOG2E_F;
        const float nh  = -0.5f * LOG2E_F;
        const float u0  = i00 * m.x + i01 * m.y;          // (Sigma^-1 mu)_0
        const float u1  = i01 * m.x + i11 * m.y;          // (Sigma^-1 mu)_1
        const float A  = nh * i00;
        const float Bc = nh * 2.0f * i01;
        const float Cc = nh * i11;
        const float D  = -2.0f * nh * u0;
        const float E  = -2.0f * nh * u1;
        const float F  = nh * (m.x * u0 + m.y * u1) + c2;
        s1[tid] = make_ulonglong2(pack2(A, A),  pack2(Bc, Bc));
        s2[tid] = make_ulonglong2(pack2(Cc, Cc), pack2(D, D));
        s3[tid] = make_ulonglong2(pack2(E, E),  pack2(F, F));
    }
    if (tid == 0) s_scale = ((const float2*)scale)[k];
    __syncthreads();

    const int halfB = B >> 1;
    const int bX = blockIdx.x * blockDim.x + tid;
    if (bX >= halfB) return;
    const int bY = bX + halfB;

    const float2 zzX = __ldg(&((const float2*)z)[(size_t)bX * K + k]);
    const float2 zzY = __ldg(&((const float2*)z)[(size_t)bY * K + k]);
    const float x0 = zzX.x, x1 = zzX.y;
    const float y0 = zzY.x, y1 = zzY.y;

    // packed monomials across the two points
    const u64 Z0  = pack2(x0, y0);
    const u64 Z1  = pack2(x1, y1);
    const u64 M00 = pack2(x0 * x0, y0 * y0);
    const u64 M01 = pack2(x0 * x1, y0 * y1);
    const u64 M11 = pack2(x1 * x1, y1 * y1);

    u64 P2 = 0ULL;
    u64 aA = 0ULL, aB = 0ULL, aC = 0ULL, aD = 0ULL, aE = 0ULL;

    #pragma unroll 8
    for (int c = 0; c < C; c++) {
        const ulonglong2 p1 = s1[c];   // (A,A) (B,B)
        const ulonglong2 p2 = s2[c];   // (C,C) (D,D)
        const ulonglong2 p3 = s3[c];   // (E,E) (F,F)
        u64 t = fma2(p1.x, M00, p3.y);
        t = fma2(p1.y, M01, t);
        t = fma2(p2.x, M11, t);
        t = fma2(p2.y, Z0,  t);
        t = fma2(p3.x, Z1,  t);
        float tx, ty; unpack2(t, tx, ty);
        const u64 e = pack2(ex2_fast(tx), ex2_fast(ty));
        P2 = add2(P2, e);
        aA = fma2(e, p1.x, aA);
        aB = fma2(e, p1.y, aB);
        aC = fma2(e, p2.x, aC);
        aD = fma2(e, p2.y, aD);
        aE = fma2(e, p3.x, aE);
    }

    const float sx = s_scale.x, sy = s_scale.y;

    float PXf, PYf, AX, AY, BX, BY, CX, CY, DX, DY, EX, EY;
    unpack2(P2, PXf, PYf);
    unpack2(aA, AX, AY);
    unpack2(aB, BX, BY);
    unpack2(aC, CX, CY);
    unpack2(aD, DX, DY);
    unpack2(aE, EX, EY);

    // point X epilogue
    {
        const float gx = LN2_F * fmaf(2.0f * x0, AX, fmaf(x1, BX, DX)) * sx;
        const float gy = LN2_F * fmaf(2.0f * x1, CX, fmaf(x0, BX, EX)) * sy;
        const float dn = 1.0f / (1.0f + ex2_fast((1.0f - 2.0f * PXf) * LOG2E_F));
        const float nrm = sqrtf(gx * gx + gy * gy);
        const float mag = ex2_fast((5500.0f - nrm) * (LOG2E_F / 1100.0f));
        const float r = mag / nrm;
        ((float2*)out)[(size_t)bX * K + k] = make_float2(dn, dn);
        ((float2*)(out + gradOff))[(size_t)bX * K + k] = make_float2(gx * r, gy * r);
    }
    // point Y epilogue
    {
        const float gx = LN2_F * fmaf(2.0f * y0, AY, fmaf(y1, BY, DY)) * sx;
        const float gy = LN2_F * fmaf(2.0f * y1, CY, fmaf(y0, BY, EY)) * sy;
        const float dn = 1.0f / (1.0f + ex2_fast((1.0f - 2.0f * PYf) * LOG2E_F));
        const float nrm = sqrtf(gx * gx + gy * gy);
        const float mag = ex2_fast((5500.0f - nrm) * (LOG2E_F / 1100.0f));
        const float r = mag / nrm;
        ((float2*)out)[(size_t)bY * K + k] = make_float2(dn, dn);
        ((float2*)(out + gradOff))[(size_t)bY * K + k] = make_float2(gx * r, gy * r);
    }
}

extern "C" void kernel_launch(void* const* d_in, const int* in_sizes, int n_in,
                              void* d_out, int out_size)
{
    const float* z     = (const float*)d_in[0];  // [B,K,2]
    const float* w     = (const float*)d_in[1];  // [K,C]
    const float* mu    = (const float*)d_in[2];  // [K,C,2]
    const float* cov   = (const float*)d_in[3];  // [K,C,2,2]
    const float* scale = (const float*)d_in[4];  // [K,2]
    float* out = (float*)d_out;

    const int K = in_sizes[4] / 2;
    const int C = in_sizes[1] / K;
    const int B = in_sizes[0] / (2 * K);
    const int gradOff = out_size / 2;

    const int halfB = B / 2;
    dim3 grid((halfB + 63) / 64, K);
    recovery_policy_kernel<<<grid, 64>>>(z, w, mu, cov, scale, out,
                                         B, K, C, gradOff);
}